// round 9
// baseline (speedup 1.0000x reference)
#include <cuda_runtime.h>
#include <cuda_bf16.h>

// PINN forward-mode dual evaluation, 4 streams: v, vz, vt, vzz.
//   h = tanh(u); d = 1-h^2; hz = d*uz; ht = d*ut; hzz = d*uzz - 2*h*uz*hz
// R4: fma.rn.f32x2 packed pairs, 512 threads, tanh.approx.
// R5: explicit software pipelining of activation + weight LDS in layers 2/3.

#define D1 128
#define D2 128
#define D3 64
#define NPTS 32
#define THREADS 512

#define SMEM_BYTES 230416
#define OFF_W3 16384
#define OFF_B2 24576
#define OFF_B3 24704
#define OFF_W4 24768
#define OFF_B4 24832
#define OFF_A  24836
#define OFF_B  (24836 + 16384)

typedef unsigned long long ull;

__device__ __forceinline__ float tanh_fast(float x) {
    float y;
    asm("tanh.approx.f32 %0, %1;" : "=f"(y) : "f"(x));
    return y;
}

__device__ __forceinline__ ull dup2(float v) {
    ull r;
    unsigned u = __float_as_uint(v);
    asm("mov.b64 %0, {%1, %2};" : "=l"(r) : "r"(u), "r"(u));
    return r;
}

__device__ __forceinline__ void fma2(ull& d, ull a, ull b) {
    asm("fma.rn.f32x2 %0, %1, %2, %0;" : "+l"(d) : "l"(a), "l"(b));
}

__device__ __forceinline__ float2 unpack2(ull v) {
    float2 r;
    asm("mov.b64 {%0, %1}, %2;" : "=f"(r.x), "=f"(r.y) : "l"(v));
    return r;
}

__global__ __launch_bounds__(THREADS, 1)
void pinn_kernel(const float* __restrict__ x,
                 const float* __restrict__ W1, const float* __restrict__ b1,
                 const float* __restrict__ W2, const float* __restrict__ b2,
                 const float* __restrict__ W3, const float* __restrict__ b3,
                 const float* __restrict__ W4, const float* __restrict__ b4,
                 float* __restrict__ out, int n, int ntiles)
{
    extern __shared__ float smem[];
    float* sW2 = smem;
    float* sW3 = smem + OFF_W3;
    float* sB2 = smem + OFF_B2;
    float* sB3 = smem + OFF_B3;
    float* sW4 = smem + OFF_W4;
    float* sB4 = smem + OFF_B4;
    float4* A  = reinterpret_cast<float4*>(smem + OFF_A);
    float4* B  = reinterpret_cast<float4*>(smem + OFF_B);

    const int tid  = threadIdx.x;
    const int warp = tid >> 5;     // 0..15
    const int lane = tid & 31;

    for (int i = tid; i < D1 * D2; i += THREADS) sW2[i] = W2[i];
    for (int i = tid; i < D2 * D3; i += THREADS) sW3[i] = W3[i];
    if (tid < D2) sB2[tid] = b2[tid];
    if (tid < D3) sB3[tid] = b3[tid];
    if (tid < D3) sW4[tid] = W4[tid];
    if (tid == 0) sB4[0] = b4[0];
    __syncthreads();

    for (int tile = blockIdx.x; tile < ntiles; tile += gridDim.x) {
        const int p0 = tile * NPTS;
        int p = p0 + lane;
        if (p >= n) p = n - 1;

        // ---------------- Layer 1: 3 -> 128 (warp w: neurons w*8..+7) ------
        {
            const float xz = __ldg(&x[p * 3 + 0]);
            const float xt = __ldg(&x[p * 3 + 1]);
            const float xh = __ldg(&x[p * 3 + 2]);
            const int jb = warp * 8;
            #pragma unroll
            for (int jj = 0; jj < 8; ++jj) {
                const int j = jb + jj;
                const float w0 = __ldg(&W1[j]);
                const float w1 = __ldg(&W1[D1 + j]);
                const float w2 = __ldg(&W1[2 * D1 + j]);
                float u  = fmaf(w0, xz, fmaf(w1, xt, fmaf(w2, xh, __ldg(&b1[j]))));
                float h  = tanh_fast(u);
                float d  = fmaf(-h, h, 1.0f);
                float hz = d * w0;
                float ht = d * w1;
                float hzz = -2.0f * h * w0 * hz;
                A[j * NPTS + lane] = make_float4(h, hz, ht, hzz);
            }
        }
        __syncthreads();   // S1: A complete

        // ---------------- Layer 2: 128 -> 128 (warp w: neurons w*8..+7) ----
        {
            ull acc[4][4];
            #pragma unroll
            for (int pq = 0; pq < 4; ++pq)
                #pragma unroll
                for (int s = 0; s < 4; ++s) acc[pq][s] = 0ULL;

            const int jb = warp * 8;

            // software pipeline: prefetch i+1 while computing i
            float4 h = A[lane];
            ulonglong2 wA = *reinterpret_cast<const ulonglong2*>(sW2 + jb);
            ulonglong2 wB = *reinterpret_cast<const ulonglong2*>(sW2 + jb + 4);

            #pragma unroll 2
            for (int i = 0; i < D1; ++i) {
                const int inx = (i + 1) & (D1 - 1);   // wrap to 0 on last (rows stay valid)
                const float4 hn = A[inx * NPTS + lane];
                const ulonglong2 wAn =
                    *reinterpret_cast<const ulonglong2*>(sW2 + inx * D2 + jb);
                const ulonglong2 wBn =
                    *reinterpret_cast<const ulonglong2*>(sW2 + inx * D2 + jb + 4);

                const ull d0 = dup2(h.x);
                const ull d1 = dup2(h.y);
                const ull d2 = dup2(h.z);
                const ull d3 = dup2(h.w);
                fma2(acc[0][0], wA.x, d0); fma2(acc[0][1], wA.x, d1);
                fma2(acc[0][2], wA.x, d2); fma2(acc[0][3], wA.x, d3);
                fma2(acc[1][0], wA.y, d0); fma2(acc[1][1], wA.y, d1);
                fma2(acc[1][2], wA.y, d2); fma2(acc[1][3], wA.y, d3);
                fma2(acc[2][0], wB.x, d0); fma2(acc[2][1], wB.x, d1);
                fma2(acc[2][2], wB.x, d2); fma2(acc[2][3], wB.x, d3);
                fma2(acc[3][0], wB.y, d0); fma2(acc[3][1], wB.y, d1);
                fma2(acc[3][2], wB.y, d2); fma2(acc[3][3], wB.y, d3);

                h = hn; wA = wAn; wB = wBn;
            }

            #pragma unroll
            for (int pq = 0; pq < 4; ++pq) {
                const float2 fv  = unpack2(acc[pq][0]);
                const float2 fz  = unpack2(acc[pq][1]);
                const float2 ft  = unpack2(acc[pq][2]);
                const float2 fzz = unpack2(acc[pq][3]);
                #pragma unroll
                for (int half = 0; half < 2; ++half) {
                    const int j = jb + pq * 2 + half;
                    const float u   = (half ? fv.y  : fv.x)  + sB2[j];
                    const float uz  = (half ? fz.y  : fz.x);
                    const float ut  = (half ? ft.y  : ft.x);
                    const float uzz = (half ? fzz.y : fzz.x);
                    const float hh  = tanh_fast(u);
                    const float dd  = fmaf(-hh, hh, 1.0f);
                    const float hz  = dd * uz;
                    const float ht  = dd * ut;
                    const float hzz = fmaf(dd, uzz, -2.0f * hh * uz * hz);
                    B[j * NPTS + lane] = make_float4(hh, hz, ht, hzz);
                }
            }
        }
        __syncthreads();   // S2: layer-2 A-reads done, B complete

        // ---------------- Layer 3: 128 -> 64 (warp w: neurons w*4..+3) -----
        {
            ull acc[2][4];
            #pragma unroll
            for (int pq = 0; pq < 2; ++pq)
                #pragma unroll
                for (int s = 0; s < 4; ++s) acc[pq][s] = 0ULL;

            const int jb = warp * 4;

            float4 h = B[lane];
            ulonglong2 wA = *reinterpret_cast<const ulonglong2*>(sW3 + jb);

            #pragma unroll 2
            for (int i = 0; i < D2; ++i) {
                const int inx = (i + 1) & (D2 - 1);
                const float4 hn = B[inx * NPTS + lane];
                const ulonglong2 wAn =
                    *reinterpret_cast<const ulonglong2*>(sW3 + inx * D3 + jb);

                const ull d0 = dup2(h.x);
                const ull d1 = dup2(h.y);
                const ull d2 = dup2(h.z);
                const ull d3 = dup2(h.w);
                fma2(acc[0][0], wA.x, d0); fma2(acc[0][1], wA.x, d1);
                fma2(acc[0][2], wA.x, d2); fma2(acc[0][3], wA.x, d3);
                fma2(acc[1][0], wA.y, d0); fma2(acc[1][1], wA.y, d1);
                fma2(acc[1][2], wA.y, d2); fma2(acc[1][3], wA.y, d3);

                h = hn; wA = wAn;
            }

            #pragma unroll
            for (int pq = 0; pq < 2; ++pq) {
                const float2 fv  = unpack2(acc[pq][0]);
                const float2 fz  = unpack2(acc[pq][1]);
                const float2 ft  = unpack2(acc[pq][2]);
                const float2 fzz = unpack2(acc[pq][3]);
                #pragma unroll
                for (int half = 0; half < 2; ++half) {
                    const int j = jb + pq * 2 + half;
                    const float u   = (half ? fv.y  : fv.x)  + sB3[j];
                    const float uz  = (half ? fz.y  : fz.x);
                    const float ut  = (half ? ft.y  : ft.x);
                    const float uzz = (half ? fzz.y : fzz.x);
                    const float hh  = tanh_fast(u);
                    const float dd  = fmaf(-hh, hh, 1.0f);
                    const float hz  = dd * uz;
                    const float ht  = dd * ut;
                    const float hzz = fmaf(dd, uzz, -2.0f * hh * uz * hz);
                    A[j * NPTS + lane] = make_float4(hh, hz, ht, hzz);
                }
            }
        }
        __syncthreads();   // S3: layer-3 B-reads done, A[0..63] complete

        // ---------------- Layer 4: 64 -> 1 (warps 0-3, one stream each) ----
        if (warp < 4) {
            const int s = warp;
            float acc = (s == 0) ? sB4[0] : 0.0f;
            const float* Af = smem + OFF_A;
            #pragma unroll 8
            for (int i = 0; i < D3; ++i) {
                const float hv = Af[(i * NPTS + lane) * 4 + s];
                acc = fmaf(sW4[i], hv, acc);
            }
            const int pp = p0 + lane;
            if (pp < n) out[pp * 4 + s] = acc;
        }
        __syncthreads();   // S4: layer-4 reads done before next tile
    }
}

extern "C" void kernel_launch(void* const* d_in, const int* in_sizes, int n_in,
                              void* d_out, int out_size)
{
    const float* x  = (const float*)d_in[0];
    const float* W1 = (const float*)d_in[1];
    const float* b1 = (const float*)d_in[2];
    const float* W2 = (const float*)d_in[3];
    const float* b2 = (const float*)d_in[4];
    const float* W3 = (const float*)d_in[5];
    const float* b3 = (const float*)d_in[6];
    const float* W4 = (const float*)d_in[7];
    const float* b4 = (const float*)d_in[8];
    float* out = (float*)d_out;

    const int n = in_sizes[0] / 3;
    const int ntiles = (n + NPTS - 1) / NPTS;

    int sms = 148;
    (void)cudaDeviceGetAttribute(&sms, cudaDevAttrMultiProcessorCount, 0);

    (void)cudaFuncSetAttribute(pinn_kernel,
                               cudaFuncAttributeMaxDynamicSharedMemorySize, SMEM_BYTES);

    int grid = sms;
    if (grid > ntiles) grid = ntiles;
    pinn_kernel<<<grid, THREADS, SMEM_BYTES>>>(x, W1, b1, W2, b2, W3, b3, W4, b4,
                                               out, n, ntiles);
}

// round 12
// speedup vs baseline: 1.1156x; 1.1156x over previous
#include <cuda_runtime.h>
#include <cuda_bf16.h>

// PINN forward-mode dual evaluation, 4 streams: v, vz, vt, vzz.
//   h = tanh(u); d = 1-h^2; hz = d*uz; ht = d*ut; hzz = d*uzz - 2*h*uz*hz
// R4: fma.rn.f32x2 packed pairs, 512 threads, tanh.approx.  (983 us)
// R5: manual SW pipeline -> REGRESSED (ALU address math). Reverted.
// R6: R4 structure + unroll 4 + W1 cached in shared.

#define D1 128
#define D2 128
#define D3 64
#define NPTS 32
#define THREADS 512

// Shared layout (floats):
//   sW2 : [0, 16384)
//   sW3 : [16384, 24576)
//   sB2 : [24576, 24704)
//   sB3 : [24704, 24768)
//   sW4 : [24768, 24832)
//   sB4 : [24832, 24836)
//   A   : [24836, 41220)  128*32 float4 (64KB), byte 99344 (16B aligned)
//   B   : [41220, 57604)  128*32 float4 (64KB)
//   sW1 : [57604, 57988)  3*128 floats (W1 rows)
// total = 57988 floats = 231952 bytes (<= 232448 opt-in max)
#define SMEM_BYTES 231952
#define OFF_W3 16384
#define OFF_B2 24576
#define OFF_B3 24704
#define OFF_W4 24768
#define OFF_B4 24832
#define OFF_A  24836
#define OFF_B  (24836 + 16384)
#define OFF_W1 (24836 + 32768)

typedef unsigned long long ull;

__device__ __forceinline__ float tanh_fast(float x) {
    float y;
    asm("tanh.approx.f32 %0, %1;" : "=f"(y) : "f"(x));
    return y;
}

__device__ __forceinline__ ull dup2(float v) {
    ull r;
    unsigned u = __float_as_uint(v);
    asm("mov.b64 %0, {%1, %2};" : "=l"(r) : "r"(u), "r"(u));
    return r;
}

__device__ __forceinline__ void fma2(ull& d, ull a, ull b) {
    asm("fma.rn.f32x2 %0, %1, %2, %0;" : "+l"(d) : "l"(a), "l"(b));
}

__device__ __forceinline__ float2 unpack2(ull v) {
    float2 r;
    asm("mov.b64 {%0, %1}, %2;" : "=f"(r.x), "=f"(r.y) : "l"(v));
    return r;
}

__global__ __launch_bounds__(THREADS, 1)
void pinn_kernel(const float* __restrict__ x,
                 const float* __restrict__ W1, const float* __restrict__ b1,
                 const float* __restrict__ W2, const float* __restrict__ b2,
                 const float* __restrict__ W3, const float* __restrict__ b3,
                 const float* __restrict__ W4, const float* __restrict__ b4,
                 float* __restrict__ out, int n, int ntiles)
{
    extern __shared__ float smem[];
    float* sW2 = smem;
    float* sW3 = smem + OFF_W3;
    float* sB2 = smem + OFF_B2;
    float* sB3 = smem + OFF_B3;
    float* sW4 = smem + OFF_W4;
    float* sB4 = smem + OFF_B4;
    float* sW1 = smem + OFF_W1;
    float4* A  = reinterpret_cast<float4*>(smem + OFF_A);
    float4* B  = reinterpret_cast<float4*>(smem + OFF_B);

    const int tid  = threadIdx.x;
    const int warp = tid >> 5;     // 0..15
    const int lane = tid & 31;

    // Stage weights into shared once (block is persistent)
    for (int i = tid; i < D1 * D2; i += THREADS) sW2[i] = W2[i];
    for (int i = tid; i < D2 * D3; i += THREADS) sW3[i] = W3[i];
    if (tid < 3 * D1) sW1[tid] = W1[tid];
    if (tid < D2) sB2[tid] = b2[tid];
    if (tid < D3) sB3[tid] = b3[tid];
    if (tid < D3) sW4[tid] = W4[tid];
    if (tid == 0) sB4[0] = b4[0];
    __syncthreads();

    for (int tile = blockIdx.x; tile < ntiles; tile += gridDim.x) {
        const int p0 = tile * NPTS;
        int p = p0 + lane;
        if (p >= n) p = n - 1;   // safety clamp (N divisible by 32)

        // ---------------- Layer 1: 3 -> 128 (warp w: neurons w*8..+7) ------
        {
            const float xz = __ldg(&x[p * 3 + 0]);
            const float xt = __ldg(&x[p * 3 + 1]);
            const float xh = __ldg(&x[p * 3 + 2]);
            const int jb = warp * 8;
            #pragma unroll
            for (int jj = 0; jj < 8; ++jj) {
                const int j = jb + jj;
                const float w0 = sW1[j];
                const float w1 = sW1[D1 + j];
                const float w2 = sW1[2 * D1 + j];
                float u  = fmaf(w0, xz, fmaf(w1, xt, fmaf(w2, xh, __ldg(&b1[j]))));
                float h  = tanh_fast(u);
                float d  = fmaf(-h, h, 1.0f);
                float hz = d * w0;                  // uz = w0
                float ht = d * w1;                  // ut = w1
                float hzz = -2.0f * h * w0 * hz;    // uzz = 0
                A[j * NPTS + lane] = make_float4(h, hz, ht, hzz);
            }
        }
        __syncthreads();   // S1: A complete

        // ---------------- Layer 2: 128 -> 128 (warp w: neurons w*8..+7) ----
        {
            ull acc[4][4];   // [neuron pair][stream]
            #pragma unroll
            for (int pq = 0; pq < 4; ++pq)
                #pragma unroll
                for (int s = 0; s < 4; ++s) acc[pq][s] = 0ULL;

            const int jb = warp * 8;
            #pragma unroll 4
            for (int i = 0; i < D1; ++i) {
                const float4 h = A[i * NPTS + lane];
                const ull d0 = dup2(h.x);
                const ull d1 = dup2(h.y);
                const ull d2 = dup2(h.z);
                const ull d3 = dup2(h.w);
                const ulonglong2* wr =
                    reinterpret_cast<const ulonglong2*>(sW2 + i * D2 + jb);
                const ulonglong2 wA = wr[0];  // neuron pairs (0,1),(2,3)
                const ulonglong2 wB = wr[1];  // neuron pairs (4,5),(6,7)
                fma2(acc[0][0], wA.x, d0); fma2(acc[0][1], wA.x, d1);
                fma2(acc[0][2], wA.x, d2); fma2(acc[0][3], wA.x, d3);
                fma2(acc[1][0], wA.y, d0); fma2(acc[1][1], wA.y, d1);
                fma2(acc[1][2], wA.y, d2); fma2(acc[1][3], wA.y, d3);
                fma2(acc[2][0], wB.x, d0); fma2(acc[2][1], wB.x, d1);
                fma2(acc[2][2], wB.x, d2); fma2(acc[2][3], wB.x, d3);
                fma2(acc[3][0], wB.y, d0); fma2(acc[3][1], wB.y, d1);
                fma2(acc[3][2], wB.y, d2); fma2(acc[3][3], wB.y, d3);
            }
            #pragma unroll
            for (int pq = 0; pq < 4; ++pq) {
                const float2 fv  = unpack2(acc[pq][0]);
                const float2 fz  = unpack2(acc[pq][1]);
                const float2 ft  = unpack2(acc[pq][2]);
                const float2 fzz = unpack2(acc[pq][3]);
                #pragma unroll
                for (int half = 0; half < 2; ++half) {
                    const int j = jb + pq * 2 + half;
                    const float u   = (half ? fv.y  : fv.x)  + sB2[j];
                    const float uz  = (half ? fz.y  : fz.x);
                    const float ut  = (half ? ft.y  : ft.x);
                    const float uzz = (half ? fzz.y : fzz.x);
                    const float hh  = tanh_fast(u);
                    const float dd  = fmaf(-hh, hh, 1.0f);
                    const float hz  = dd * uz;
                    const float ht  = dd * ut;
                    const float hzz = fmaf(dd, uzz, -2.0f * hh * uz * hz);
                    B[j * NPTS + lane] = make_float4(hh, hz, ht, hzz);
                }
            }
        }
        __syncthreads();   // S2: layer-2 A-reads done, B complete

        // ---------------- Layer 3: 128 -> 64 (warp w: neurons w*4..+3) -----
        {
            ull acc[2][4];
            #pragma unroll
            for (int pq = 0; pq < 2; ++pq)
                #pragma unroll
                for (int s = 0; s < 4; ++s) acc[pq][s] = 0ULL;

            const int jb = warp * 4;
            #pragma unroll 4
            for (int i = 0; i < D2; ++i) {
                const float4 h = B[i * NPTS + lane];
                const ull d0 = dup2(h.x);
                const ull d1 = dup2(h.y);
                const ull d2 = dup2(h.z);
                const ull d3 = dup2(h.w);
                const ulonglong2 wA =
                    *reinterpret_cast<const ulonglong2*>(sW3 + i * D3 + jb);
                fma2(acc[0][0], wA.x, d0); fma2(acc[0][1], wA.x, d1);
                fma2(acc[0][2], wA.x, d2); fma2(acc[0][3], wA.x, d3);
                fma2(acc[1][0], wA.y, d0); fma2(acc[1][1], wA.y, d1);
                fma2(acc[1][2], wA.y, d2); fma2(acc[1][3], wA.y, d3);
            }
            #pragma unroll
            for (int pq = 0; pq < 2; ++pq) {
                const float2 fv  = unpack2(acc[pq][0]);
                const float2 fz  = unpack2(acc[pq][1]);
                const float2 ft  = unpack2(acc[pq][2]);
                const float2 fzz = unpack2(acc[pq][3]);
                #pragma unroll
                for (int half = 0; half < 2; ++half) {
                    const int j = jb + pq * 2 + half;
                    const float u   = (half ? fv.y  : fv.x)  + sB3[j];
                    const float uz  = (half ? fz.y  : fz.x);
                    const float ut  = (half ? ft.y  : ft.x);
                    const float uzz = (half ? fzz.y : fzz.x);
                    const float hh  = tanh_fast(u);
                    const float dd  = fmaf(-hh, hh, 1.0f);
                    const float hz  = dd * uz;
                    const float ht  = dd * ut;
                    const float hzz = fmaf(dd, uzz, -2.0f * hh * uz * hz);
                    A[j * NPTS + lane] = make_float4(hh, hz, ht, hzz);
                }
            }
        }
        __syncthreads();   // S3: layer-3 B-reads done, A[0..63] complete

        // ---------------- Layer 4: 64 -> 1 (warps 0-3, one stream each) ----
        if (warp < 4) {
            const int s = warp;
            float acc = (s == 0) ? sB4[0] : 0.0f;
            const float* Af = smem + OFF_A;
            #pragma unroll 16
            for (int i = 0; i < D3; ++i) {
                const float hv = Af[(i * NPTS + lane) * 4 + s];
                acc = fmaf(sW4[i], hv, acc);
            }
            const int pp = p0 + lane;
            if (pp < n) out[pp * 4 + s] = acc;
        }
        __syncthreads();   // S4: layer-4 reads done before next tile
    }
}

extern "C" void kernel_launch(void* const* d_in, const int* in_sizes, int n_in,
                              void* d_out, int out_size)
{
    const float* x  = (const float*)d_in[0];
    const float* W1 = (const float*)d_in[1];
    const float* b1 = (const float*)d_in[2];
    const float* W2 = (const float*)d_in[3];
    const float* b2 = (const float*)d_in[4];
    const float* W3 = (const float*)d_in[5];
    const float* b3 = (const float*)d_in[6];
    const float* W4 = (const float*)d_in[7];
    const float* b4 = (const float*)d_in[8];
    float* out = (float*)d_out;

    const int n = in_sizes[0] / 3;
    const int ntiles = (n + NPTS - 1) / NPTS;

    int sms = 148;
    (void)cudaDeviceGetAttribute(&sms, cudaDevAttrMultiProcessorCount, 0);

    (void)cudaFuncSetAttribute(pinn_kernel,
                               cudaFuncAttributeMaxDynamicSharedMemorySize, SMEM_BYTES);

    int grid = sms;
    if (grid > ntiles) grid = ntiles;
    pinn_kernel<<<grid, THREADS, SMEM_BYTES>>>(x, W1, b1, W2, b2, W3, b3, W4, b4,
                                               out, n, ntiles);
}